// round 3
// baseline (speedup 1.0000x reference)
#include <cuda_runtime.h>

#define NN 192
#define CC 16
#define MM 16
#define K32 32

// ---------------- scratch (device globals; no runtime allocation) ----------------
static __device__ float2 g_A [(size_t)CC*NN*MM*NN];   // [c][x][kz][y]
static __device__ float2 g_B [(size_t)CC*K32*MM*NN];  // [c][kyl][kz][x]
static __device__ float2 g_Xf[(size_t)K32*K32*MM*CC]; // [kxl][kyl][kz][c]
static __device__ float2 g_Yf[(size_t)CC*K32*MM*K32]; // [o][kyl][kz][kxl]
static __device__ float2 g_G1[(size_t)CC*NN*MM*K32];  // [o][x][kz][kyl]
static __device__ float2 g_G2[(size_t)CC*NN*MM*NN];   // [o][x][kz][y]
static __device__ float2 g_Tzf[NN*MM];   // fwd z twiddle: (cos, -sin)
static __device__ float2 g_Tzi[NN*MM];   // inv z (hermitian weighted): (w cos, w sin)
static __device__ float2 g_Fnf[NN*K32];  // fwd x/y twiddle, n-major: (cos, -sin)
static __device__ float2 g_Fki[K32*NN];  // inv x/y twiddle, k-major: (cos, +sin)

// ---------------- twiddle tables (exact integer angle reduction, double sincos) ----
__global__ void k_tables() {
    int t = threadIdx.x;
    const double TWO_PI = 6.283185307179586476925286766559;
    for (int i = t; i < NN*MM; i += 256) {
        int z = i >> 4, kz = i & 15;
        double ang = TWO_PI * (double)((z * kz) % NN) / (double)NN;
        double s, c; sincos(ang, &s, &c);
        g_Tzf[i] = make_float2((float)c, (float)(-s));
        double w = (kz == 0) ? 1.0 : 2.0;
        g_Tzi[i] = make_float2((float)(w * c), (float)(w * s));
    }
    for (int i = t; i < NN*K32; i += 256) {
        int n = i >> 5, k = i & 31;
        int K = (k < MM) ? k : (k + 160);       // {0..15, 176..191}
        double ang = TWO_PI * (double)((n * K) % NN) / (double)NN;
        double s, c; sincos(ang, &s, &c);
        g_Fnf[n*K32 + k] = make_float2((float)c, (float)(-s));
        g_Fki[k*NN + n]  = make_float2((float)c, (float)(s));
    }
}

// ---------------- stage 1: forward DFT along z (real -> 16 complex) ----------------
// rows = (c,x,y) linear; 64 rows/block; thread = (row-quad, kz)
__global__ __launch_bounds__(256) void k_fz(const float* __restrict__ x) {
    extern __shared__ float sm[];
    float*  xs = sm;                        // 64 * 193
    float2* tz = (float2*)(sm + 64*193);    // 192*16
    const int tid = threadIdx.x;
    const size_t rbase = (size_t)blockIdx.x * 64;
    const float* src = x + rbase * NN;
    for (int i = tid; i < 64*NN; i += 256) {
        int r = i / NN, z = i - r*NN;
        xs[r*193 + z] = src[i];
    }
    for (int i = tid; i < NN*MM; i += 256) tz[i] = g_Tzf[i];
    __syncthreads();
    const int kz = tid & 15, rq = tid >> 4;
    float ar0=0.f, ai0=0.f, ar1=0.f, ai1=0.f, ar2=0.f, ai2=0.f, ar3=0.f, ai3=0.f;
    const float* xr = xs + rq*4*193;
#pragma unroll 4
    for (int z = 0; z < NN; z++) {
        float2 t = tz[z*MM + kz];
        float v0 = xr[z];
        float v1 = xr[193 + z];
        float v2 = xr[2*193 + z];
        float v3 = xr[3*193 + z];
        ar0 = fmaf(v0, t.x, ar0); ai0 = fmaf(v0, t.y, ai0);
        ar1 = fmaf(v1, t.x, ar1); ai1 = fmaf(v1, t.y, ai1);
        ar2 = fmaf(v2, t.x, ar2); ai2 = fmaf(v2, t.y, ai2);
        ar3 = fmaf(v3, t.x, ar3); ai3 = fmaf(v3, t.y, ai3);
    }
    const size_t cx = rbase / NN;           // block fully inside one (c,x)
    const int y0 = (int)(rbase - cx*NN) + rq*4;
    float2* dst = g_A + (cx*MM + kz)*NN;
    dst[y0+0] = make_float2(ar0, ai0);
    dst[y0+1] = make_float2(ar1, ai1);
    dst[y0+2] = make_float2(ar2, ai2);
    dst[y0+3] = make_float2(ar3, ai3);
}

// ---------------- stage 2: forward DFT along y (192 complex -> 32 modes) -----------
// rows = (c,x,kz); A row contiguous. 8 rows/block; thread = (row, kyl)
__global__ __launch_bounds__(256) void k_fy() {
    extern __shared__ float2 sm2[];
    float2* as = sm2;               // 8 * 193
    float2* tw = sm2 + 8*193;       // 192 * 32
    const int tid = threadIdx.x;
    const size_t rbase = (size_t)blockIdx.x * 8;
    const float2* src = g_A + rbase * NN;
    for (int i = tid; i < 8*NN; i += 256) {
        int r = i / NN, y = i - r*NN;
        as[r*193 + y] = src[i];
    }
    for (int i = tid; i < NN*K32; i += 256) tw[i] = g_Fnf[i];
    __syncthreads();
    const int kyl = tid & 31, r = tid >> 5;
    float re = 0.f, im = 0.f;
    const float2* arow = as + r*193;
#pragma unroll 4
    for (int y = 0; y < NN; y++) {
        float2 a = arow[y];
        float2 w = tw[y*K32 + kyl];
        re = fmaf(a.x, w.x, re); re = fmaf(-a.y, w.y, re);
        im = fmaf(a.x, w.y, im); im = fmaf(a.y, w.x, im);
    }
    const size_t row = rbase + r;
    const int kz = (int)(row & 15);
    const size_t cx = row >> 4;
    const int c = (int)(cx / NN), xx = (int)(cx % NN);
    g_B[(((size_t)c*K32 + kyl)*MM + kz)*NN + xx] = make_float2(re, im);
}

// ---------------- stage 3: forward DFT along x (192 complex -> 32 modes) -----------
// rows = (c,kyl,kz); B row contiguous. 8 rows/block; thread = (row, kxl)
__global__ __launch_bounds__(256) void k_fx() {
    extern __shared__ float2 sm2[];
    float2* as = sm2;
    float2* tw = sm2 + 8*193;
    const int tid = threadIdx.x;
    const size_t rbase = (size_t)blockIdx.x * 8;
    const float2* src = g_B + rbase * NN;
    for (int i = tid; i < 8*NN; i += 256) {
        int r = i / NN, xx = i - r*NN;
        as[r*193 + xx] = src[i];
    }
    for (int i = tid; i < NN*K32; i += 256) tw[i] = g_Fnf[i];
    __syncthreads();
    const int kxl = tid & 31, r = tid >> 5;
    float re = 0.f, im = 0.f;
    const float2* arow = as + r*193;
#pragma unroll 4
    for (int xx = 0; xx < NN; xx++) {
        float2 a = arow[xx];
        float2 w = tw[xx*K32 + kxl];
        re = fmaf(a.x, w.x, re); re = fmaf(-a.y, w.y, re);
        im = fmaf(a.x, w.y, im); im = fmaf(a.y, w.x, im);
    }
    const size_t row = rbase + r;
    const int kz = (int)(row & 15);
    const size_t t2 = row >> 4;
    const int kyl = (int)(t2 & 31), c = (int)(t2 >> 5);
    g_Xf[(((size_t)kxl*K32 + kyl)*MM + kz)*CC + c] = make_float2(re, im);
}

// ---------------- stage M: per-mode 16x16 complex channel mixing -------------------
// block = one (kxl,kyl); thread = (o, kz); scale 1/192^3 folded in
__global__ __launch_bounds__(256) void k_mix(const float* __restrict__ wr,
                                             const float* __restrict__ wi) {
    __shared__ float2 xfs[256];     // [i][kz]
    const int tid = threadIdx.x;
    const int kxl = blockIdx.x >> 5, kyl = blockIdx.x & 31;
    const int b   = (kxl >= MM ? 1 : 0) + (kyl >= MM ? 2 : 0);
    const int kxm = kxl & 15, kym = kyl & 15;
    {   // Xf tile is contiguous: [(kxl*32+kyl)*256 + kz*16 + i]
        float2 v = g_Xf[((size_t)(kxl*K32 + kyl))*256 + tid];
        int kz = tid >> 4, i = tid & 15;
        xfs[i*MM + kz] = v;         // transpose so compute reads are conflict-free
    }
    __syncthreads();
    const int o = tid >> 4, kz = tid & 15;
    float re = 0.f, im = 0.f;
    const size_t wb = ((((size_t)b*MM)*MM + o)*MM + kxm)*MM*MM + (size_t)kym*MM + kz;
#pragma unroll
    for (int i = 0; i < MM; i++) {
        float2 xf = xfs[i*MM + kz];
        size_t widx = wb + (size_t)i * (MM*MM*MM*MM);   // i stride = 16^4
        float a = wr[widx], c = wi[widx];
        re = fmaf(xf.x, a, re); re = fmaf(-xf.y, c, re);
        im = fmaf(xf.x, c, im); im = fmaf(xf.y, a, im);
    }
    const float s = 1.0f / 7077888.0f;  // 1/192^3
    g_Yf[(((size_t)o*K32 + kyl)*MM + kz)*K32 + kxl] = make_float2(re*s, im*s);
}

// ---------------- stage 4: inverse DFT along x (32 modes -> 192) -------------------
// rows = (o,kyl,kz); Yf row contiguous. 32 rows/block; thread = x; twiddles in regs
__global__ __launch_bounds__(192) void k_ix() {
    __shared__ float2 ys[32*K32];
    const int tid = threadIdx.x;     // = x
    const size_t rbase = (size_t)blockIdx.x * 32;
    const float2* src = g_Yf + rbase * K32;
    for (int i = tid; i < 32*K32; i += 192) ys[i] = src[i];
    __syncthreads();
    float twx[K32], twy[K32];
#pragma unroll
    for (int k = 0; k < K32; k++) {
        float2 w = g_Fki[k*NN + tid];
        twx[k] = w.x; twy[k] = w.y;
    }
    for (int r = 0; r < 32; r++) {
        float re = 0.f, im = 0.f;
        const float2* yr = ys + r*K32;
#pragma unroll
        for (int k = 0; k < K32; k++) {
            float2 v = yr[k];
            re = fmaf(v.x, twx[k], re); re = fmaf(-v.y, twy[k], re);
            im = fmaf(v.x, twy[k], im); im = fmaf(v.y, twx[k], im);
        }
        const size_t row = rbase + r;
        const int kz = (int)(row & 15);
        const size_t t2 = row >> 4;
        const int kyl = (int)(t2 & 31), o = (int)(t2 >> 5);
        g_G1[(((size_t)o*NN + tid)*MM + kz)*K32 + kyl] = make_float2(re, im);
    }
}

// ---------------- stage 5: inverse DFT along y (32 modes -> 192) -------------------
// rows = (o,x,kz); G1 row contiguous; output G2[row*192 + y] (coalesced)
__global__ __launch_bounds__(192) void k_iy() {
    __shared__ float2 ys[32*K32];
    const int tid = threadIdx.x;     // = y
    const size_t rbase = (size_t)blockIdx.x * 32;
    const float2* src = g_G1 + rbase * K32;
    for (int i = tid; i < 32*K32; i += 192) ys[i] = src[i];
    __syncthreads();
    float twx[K32], twy[K32];
#pragma unroll
    for (int k = 0; k < K32; k++) {
        float2 w = g_Fki[k*NN + tid];
        twx[k] = w.x; twy[k] = w.y;
    }
    for (int r = 0; r < 32; r++) {
        float re = 0.f, im = 0.f;
        const float2* yr = ys + r*K32;
#pragma unroll
        for (int k = 0; k < K32; k++) {
            float2 v = yr[k];
            re = fmaf(v.x, twx[k], re); re = fmaf(-v.y, twy[k], re);
            im = fmaf(v.x, twy[k], im); im = fmaf(v.y, twx[k], im);
        }
        g_G2[(rbase + r)*NN + tid] = make_float2(re, im);
    }
}

// ---------------- stage 6: inverse real DFT along z (16 complex -> 192 real) -------
// block = one (o,x); thread = z; hermitian weights already folded into table
__global__ __launch_bounds__(192) void k_iz(float* __restrict__ out) {
    extern __shared__ float2 gs[];          // 16*192 = 24 KB dynamic
    __shared__ float2 tzs[NN*MM];           // 24 KB static
    const int tid = threadIdx.x;            // = z
    const size_t bi = blockIdx.x;
    const float2* src = g_G2 + bi * (MM*NN);
    for (int i = tid; i < MM*NN; i += 192) { gs[i] = src[i]; tzs[i] = g_Tzi[i]; }
    __syncthreads();
    float tc[MM], ts[MM];
#pragma unroll
    for (int kz = 0; kz < MM; kz++) {
        float2 v = tzs[tid*MM + kz];
        tc[kz] = v.x; ts[kz] = -v.y;
    }
    float* dst = out + bi * (size_t)(NN*NN);
    for (int y = 0; y < NN; y++) {
        float acc = 0.f;
#pragma unroll
        for (int kz = 0; kz < MM; kz++) {
            float2 g = gs[kz*NN + y];
            acc = fmaf(g.x, tc[kz], acc);
            acc = fmaf(g.y, ts[kz], acc);
        }
        dst[(size_t)y*NN + tid] = acc;
    }
}

// ---------------- launch ------------------------------------------------------------
extern "C" void kernel_launch(void* const* d_in, const int* in_sizes, int n_in,
                              void* d_out, int out_size) {
    (void)in_sizes; (void)n_in; (void)out_size;
    const float* x  = (const float*)d_in[0];
    const float* wr = (const float*)d_in[1];
    const float* wi = (const float*)d_in[2];
    float* out = (float*)d_out;

    const int SM1 = 64*193*4 + NN*MM*8;              // 73984 B
    const int SM2 = (8*193 + NN*K32) * 8;            // 61504 B
    const int SM6 = MM*NN*8;                         // 24576 B

    cudaFuncSetAttribute(k_fz, cudaFuncAttributeMaxDynamicSharedMemorySize, SM1);
    cudaFuncSetAttribute(k_fy, cudaFuncAttributeMaxDynamicSharedMemorySize, SM2);
    cudaFuncSetAttribute(k_fx, cudaFuncAttributeMaxDynamicSharedMemorySize, SM2);
    cudaFuncSetAttribute(k_iz, cudaFuncAttributeMaxDynamicSharedMemorySize, SM6);

    k_tables<<<1, 256>>>();
    k_fz <<<(CC*NN*NN)/64, 256, SM1>>>(x);       // 9216 blocks
    k_fy <<<(CC*NN*MM)/8,  256, SM2>>>();        // 6144 blocks
    k_fx <<<(CC*K32*MM)/8, 256, SM2>>>();        // 1024 blocks
    k_mix<<<K32*K32,       256>>>(wr, wi);       // 1024 blocks
    k_ix <<<(CC*K32*MM)/32, 192>>>();            // 256 blocks
    k_iy <<<(CC*NN*MM)/32,  192>>>();            // 1536 blocks
    k_iz <<<CC*NN, 192, SM6>>>(out);             // 3072 blocks
}

// round 5
// speedup vs baseline: 1.1383x; 1.1383x over previous
#include <cuda_runtime.h>

#define NN 192
#define CC 16
#define MM 16
#define K32 32
typedef unsigned long long u64;

__device__ __forceinline__ u64 fma2(u64 a, u64 b, u64 c) {
    u64 d; asm("fma.rn.f32x2 %0,%1,%2,%3;" : "=l"(d) : "l"(a), "l"(b), "l"(c)); return d;
}
__device__ __forceinline__ float2 up2(u64 v) {
    float2 r; asm("mov.b64 {%0,%1},%2;" : "=f"(r.x), "=f"(r.y) : "l"(v)); return r;
}
__device__ __forceinline__ u64 pk2(float a, float b) {
    u64 v; asm("mov.b64 %0,{%1,%2};" : "=l"(v) : "f"(a), "f"(b)); return v;
}

// ---------------- scratch (device globals; no runtime allocation) ----------------
static __device__ float2 g_A [(size_t)CC*NN*MM*NN];   // [c][x][kz][y]
static __device__ float2 g_B [(size_t)CC*K32*MM*NN];  // [c][kyl][kz][x]
static __device__ float2 g_Xf[(size_t)K32*K32*MM*CC]; // [kxl][kyl][kz][c]
static __device__ float2 g_Yf[(size_t)CC*K32*MM*K32]; // [o][kyl][kz][kxl]
static __device__ float2 g_G1[(size_t)CC*NN*MM*K32];  // [o][x][kz][kyl]
static __device__ float2 g_G2[(size_t)CC*NN*MM*NN];   // [o][x][kz][y]
static __device__ float2 g_Tzf[NN*MM];   // fwd z twiddle: (cos, -sin)
static __device__ float2 g_Tzi[NN*MM];   // inv z (hermitian weighted): (w cos, w sin)
static __device__ float2 g_Fnf[NN*K32];  // fwd x/y twiddle, n-major: (cos, -sin)
static __device__ float2 g_Fki[K32*NN];  // inv x/y twiddle, k-major: (cos, +sin)

// ---------------- twiddle tables (exact integer angle reduction, double sincos) ----
__global__ void k_tables() {
    int t = threadIdx.x;
    const double TWO_PI = 6.283185307179586476925286766559;
    for (int i = t; i < NN*MM; i += 256) {
        int z = i >> 4, kz = i & 15;
        double ang = TWO_PI * (double)((z * kz) % NN) / (double)NN;
        double s, c; sincos(ang, &s, &c);
        g_Tzf[i] = make_float2((float)c, (float)(-s));
        double w = (kz == 0) ? 1.0 : 2.0;
        g_Tzi[i] = make_float2((float)(w * c), (float)(w * s));
    }
    for (int i = t; i < NN*K32; i += 256) {
        int n = i >> 5, k = i & 31;
        int K = (k < MM) ? k : (k + 160);       // {0..15, 176..191}
        double ang = TWO_PI * (double)((n * K) % NN) / (double)NN;
        double s, c; sincos(ang, &s, &c);
        g_Fnf[n*K32 + k] = make_float2((float)c, (float)(-s));
        g_Fki[k*NN + n]  = make_float2((float)c, (float)(s));
    }
}

// ---------------- stage 1: forward DFT along z (real -> 16 complex) ----------------
// radix-2 fold: X[kz] = sum_{z<96} (x[z] +/- x[z+96]) * w(z,kz), sign by kz parity.
// block = 64 rows (one third of one (c,x)); 128 threads = 16 kz x 8 row-octets.
// smem holds fold planes TRANSPOSED [z][row] so row-pairs load as packed b64.
__global__ __launch_bounds__(128) void k_fz(const float* __restrict__ x) {
    extern __shared__ float sm[];
    float*  xsE = sm;                        // [96][66]
    float*  xsO = sm + 96*66;                // [96][66]
    float4* t4  = (float4*)(sm + 2*96*66);   // [96][16]: (c,c,-s,-s)
    const int tid = threadIdx.x;
    const size_t rbase = (size_t)blockIdx.x * 64;
    const float* src = x + rbase * NN;
    for (int i = tid; i < 64*96; i += 128) {
        int r = i / 96, z = i - r*96;
        float a = src[r*NN + z];
        float b = src[r*NN + z + 96];
        xsE[z*66 + r] = a + b;
        xsO[z*66 + r] = a - b;
    }
    for (int i = tid; i < 96*MM; i += 128) {
        float2 w = g_Tzf[i];
        t4[i] = make_float4(w.x, w.x, w.y, w.y);
    }
    __syncthreads();
    const int kz = tid & 15, rq = tid >> 4;
    const float* xs = (kz & 1) ? xsO : xsE;
    u64 ar0=0,ar1=0,ar2=0,ar3=0, ai0=0,ai1=0,ai2=0,ai3=0;
#pragma unroll 2
    for (int z = 0; z < 96; z++) {
        ulonglong2 t = *(const ulonglong2*)&t4[z*MM + kz];
        const u64* vp = (const u64*)(xs + z*66 + rq*8);
        u64 v0 = vp[0], v1 = vp[1], v2 = vp[2], v3 = vp[3];
        ar0 = fma2(v0, t.x, ar0); ai0 = fma2(v0, t.y, ai0);
        ar1 = fma2(v1, t.x, ar1); ai1 = fma2(v1, t.y, ai1);
        ar2 = fma2(v2, t.x, ar2); ai2 = fma2(v2, t.y, ai2);
        ar3 = fma2(v3, t.x, ar3); ai3 = fma2(v3, t.y, ai3);
    }
    const size_t cx = rbase / NN;
    const int y0 = (int)(rbase - cx*NN) + rq*8;
    float2* dst = g_A + (cx*MM + kz)*NN + y0;
    float2 r, i2;
    r = up2(ar0); i2 = up2(ai0); dst[0] = make_float2(r.x, i2.x); dst[1] = make_float2(r.y, i2.y);
    r = up2(ar1); i2 = up2(ai1); dst[2] = make_float2(r.x, i2.x); dst[3] = make_float2(r.y, i2.y);
    r = up2(ar2); i2 = up2(ai2); dst[4] = make_float2(r.x, i2.x); dst[5] = make_float2(r.y, i2.y);
    r = up2(ar3); i2 = up2(ai3); dst[6] = make_float2(r.x, i2.x); dst[7] = make_float2(r.y, i2.y);
}

// ---------------- stage 2: forward DFT along y (fold + f32x2 horizontal) -----------
// block = 16 rows = one (c,x) (all 16 kz); 256 threads = 32 kyl x 8 row-pairs.
// complex MAC: acc += (ax,ay)*(wx,-wy) -> re = hsum; acc2 += (ax,ay)*(wy,wx) -> im.
__global__ __launch_bounds__(256) void k_fy() {
    extern __shared__ float2 smf2[];
    float2* aE = smf2;                        // [96][17]
    float2* aO = smf2 + 96*17;                // [96][17]
    float4* t4 = (float4*)(smf2 + 2*96*17);   // [96][32]: (wx,-wy,wy,wx)
    const int tid = threadIdx.x;
    const size_t rbase = (size_t)blockIdx.x * 16;
    const float2* src = g_A + rbase * NN;
    for (int i = tid; i < 16*96; i += 256) {
        int r = i / 96, y = i - r*96;
        float2 a = src[r*NN + y];
        float2 b = src[r*NN + y + 96];
        aE[y*17 + r] = make_float2(a.x + b.x, a.y + b.y);
        aO[y*17 + r] = make_float2(a.x - b.x, a.y - b.y);
    }
    for (int i = tid; i < 96*K32; i += 256) {
        int y = i >> 5, k = i & 31;
        float2 w = g_Fnf[y*K32 + k];
        t4[i] = make_float4(w.x, -w.y, w.y, w.x);
    }
    __syncthreads();
    const int kyl = tid & 31, rp = tid >> 5;
    const float2* pl = (kyl & 1) ? aO : aE;
    u64 R0=0, I0=0, R1=0, I1=0;
#pragma unroll 2
    for (int y = 0; y < 96; y++) {
        u64 a0 = *(const u64*)&pl[y*17 + 2*rp];
        u64 a1 = *(const u64*)&pl[y*17 + 2*rp + 1];
        ulonglong2 t = *(const ulonglong2*)&t4[y*K32 + kyl];
        R0 = fma2(a0, t.x, R0); I0 = fma2(a0, t.y, I0);
        R1 = fma2(a1, t.x, R1); I1 = fma2(a1, t.y, I1);
    }
    const int c  = (int)(blockIdx.x / NN);
    const int xx = (int)(blockIdx.x % NN);
    float2 r0 = up2(R0), i0 = up2(I0), r1 = up2(R1), i1 = up2(I1);
    int kz0 = 2*rp, kz1 = 2*rp + 1;
    g_B[(((size_t)c*K32 + kyl)*MM + kz0)*NN + xx] = make_float2(r0.x + r0.y, i0.x + i0.y);
    g_B[(((size_t)c*K32 + kyl)*MM + kz1)*NN + xx] = make_float2(r1.x + r1.y, i1.x + i1.y);
}

// ---------------- stage 3: forward DFT along x (192 complex -> 32 modes) -----------
__global__ __launch_bounds__(256) void k_fx() {
    extern __shared__ float2 sm2[];
    float2* as = sm2;
    float2* tw = sm2 + 8*193;
    const int tid = threadIdx.x;
    const size_t rbase = (size_t)blockIdx.x * 8;
    const float2* src = g_B + rbase * NN;
    for (int i = tid; i < 8*NN; i += 256) {
        int r = i / NN, xx = i - r*NN;
        as[r*193 + xx] = src[i];
    }
    for (int i = tid; i < NN*K32; i += 256) tw[i] = g_Fnf[i];
    __syncthreads();
    const int kxl = tid & 31, r = tid >> 5;
    float re = 0.f, im = 0.f;
    const float2* arow = as + r*193;
#pragma unroll 4
    for (int xx = 0; xx < NN; xx++) {
        float2 a = arow[xx];
        float2 w = tw[xx*K32 + kxl];
        re = fmaf(a.x, w.x, re); re = fmaf(-a.y, w.y, re);
        im = fmaf(a.x, w.y, im); im = fmaf(a.y, w.x, im);
    }
    const size_t row = rbase + r;
    const int kz = (int)(row & 15);
    const size_t t2 = row >> 4;
    const int kyl = (int)(t2 & 31), c = (int)(t2 >> 5);
    g_Xf[(((size_t)kxl*K32 + kyl)*MM + kz)*CC + c] = make_float2(re, im);
}

// ---------------- stage M: per-mode 16x16 complex channel mixing -------------------
__global__ __launch_bounds__(256) void k_mix(const float* __restrict__ wr,
                                             const float* __restrict__ wi) {
    __shared__ float2 xfs[256];
    const int tid = threadIdx.x;
    const int kxl = blockIdx.x >> 5, kyl = blockIdx.x & 31;
    const int b   = (kxl >= MM ? 1 : 0) + (kyl >= MM ? 2 : 0);
    const int kxm = kxl & 15, kym = kyl & 15;
    {
        float2 v = g_Xf[((size_t)(kxl*K32 + kyl))*256 + tid];
        int kz = tid >> 4, i = tid & 15;
        xfs[i*MM + kz] = v;
    }
    __syncthreads();
    const int o = tid >> 4, kz = tid & 15;
    float re = 0.f, im = 0.f;
    const size_t wb = ((((size_t)b*MM)*MM + o)*MM + kxm)*MM*MM + (size_t)kym*MM + kz;
#pragma unroll
    for (int i = 0; i < MM; i++) {
        float2 xf = xfs[i*MM + kz];
        size_t widx = wb + (size_t)i * (MM*MM*MM*MM);
        float a = wr[widx], c = wi[widx];
        re = fmaf(xf.x, a, re); re = fmaf(-xf.y, c, re);
        im = fmaf(xf.x, c, im); im = fmaf(xf.y, a, im);
    }
    const float s = 1.0f / 7077888.0f;  // 1/192^3
    g_Yf[(((size_t)o*K32 + kyl)*MM + kz)*K32 + kxl] = make_float2(re*s, im*s);
}

// ---------------- stage 4: inverse DFT along x (32 modes -> 192, output fold) ------
// thread = x in [0,96); even/odd-k partial sums give x and x+96 together.
__global__ __launch_bounds__(96) void k_ix() {
    __shared__ __align__(16) float2 ys[32*K32];
    const int tid = threadIdx.x;
    const size_t rbase = (size_t)blockIdx.x * 32;
    const float2* src = g_Yf + rbase * K32;
    for (int i = tid; i < 32*K32; i += 96) ys[i] = src[i];
    __syncthreads();
    float twx[K32], twy[K32];
#pragma unroll
    for (int k = 0; k < K32; k++) {
        float2 w = g_Fki[k*NN + tid];
        twx[k] = w.x; twy[k] = w.y;
    }
    for (int r = 0; r < 32; r++) {
        float arp=0.f, arm=0.f, aip=0.f, aiq=0.f;
        float brp=0.f, brm=0.f, bip=0.f, biq=0.f;
        const float2* yr = ys + r*K32;
#pragma unroll
        for (int k = 0; k < K32; k++) {
            float2 v = yr[k];
            if (k & 1) {
                brp = fmaf(v.x, twx[k], brp); brm = fmaf(v.y, twy[k], brm);
                bip = fmaf(v.x, twy[k], bip); biq = fmaf(v.y, twx[k], biq);
            } else {
                arp = fmaf(v.x, twx[k], arp); arm = fmaf(v.y, twy[k], arm);
                aip = fmaf(v.x, twy[k], aip); aiq = fmaf(v.y, twx[k], aiq);
            }
        }
        float reA = arp - arm, imA = aip + aiq;
        float reB = brp - brm, imB = bip + biq;
        const size_t row = rbase + r;
        const int kz  = (int)(row & 15);
        const int kyl = (int)((row >> 4) & 31);
        const int o   = (int)(row >> 9);
        g_G1[(((size_t)o*NN + tid)*MM + kz)*K32 + kyl]        = make_float2(reA + reB, imA + imB);
        g_G1[(((size_t)o*NN + tid + 96)*MM + kz)*K32 + kyl]   = make_float2(reA - reB, imA - imB);
    }
}

// ---------------- stage 5: inverse DFT along y (32 modes -> 192, output fold) ------
__global__ __launch_bounds__(96) void k_iy() {
    __shared__ __align__(16) float2 ys[32*K32];
    const int tid = threadIdx.x;     // y in [0,96)
    const size_t rbase = (size_t)blockIdx.x * 32;
    const float2* src = g_G1 + rbase * K32;
    for (int i = tid; i < 32*K32; i += 96) ys[i] = src[i];
    __syncthreads();
    float twx[K32], twy[K32];
#pragma unroll
    for (int k = 0; k < K32; k++) {
        float2 w = g_Fki[k*NN + tid];
        twx[k] = w.x; twy[k] = w.y;
    }
    for (int r = 0; r < 32; r++) {
        float arp=0.f, arm=0.f, aip=0.f, aiq=0.f;
        float brp=0.f, brm=0.f, bip=0.f, biq=0.f;
        const float2* yr = ys + r*K32;
#pragma unroll
        for (int k = 0; k < K32; k++) {
            float2 v = yr[k];
            if (k & 1) {
                brp = fmaf(v.x, twx[k], brp); brm = fmaf(v.y, twy[k], brm);
                bip = fmaf(v.x, twy[k], bip); biq = fmaf(v.y, twx[k], biq);
            } else {
                arp = fmaf(v.x, twx[k], arp); arm = fmaf(v.y, twy[k], arm);
                aip = fmaf(v.x, twy[k], aip); aiq = fmaf(v.y, twx[k], aiq);
            }
        }
        float reA = arp - arm, imA = aip + aiq;
        float reB = brp - brm, imB = bip + biq;
        const size_t row = rbase + r;
        g_G2[row*NN + tid]      = make_float2(reA + reB, imA + imB);
        g_G2[row*NN + tid + 96] = make_float2(reA - reB, imA - imB);
    }
}

// ---------------- stage 6: inverse real DFT along z (fold + f32x2 horizontal) ------
// thread = z in [0,96); 16 packed twiddles (tc,ts) live in registers; the
// even/odd-kz split yields out[z] and out[z+96] from one pass over kz.
__global__ __launch_bounds__(96) void k_iz(float* __restrict__ out) {
    __shared__ __align__(16) float2 sg[MM*NN];   // [kz][y]
    const int tid = threadIdx.x;
    const size_t bi = blockIdx.x;
    const float2* src = g_G2 + bi * (MM*NN);
    for (int i = tid; i < MM*NN; i += 96) sg[i] = src[i];
    u64 tw[MM];
#pragma unroll
    for (int kz = 0; kz < MM; kz++) {
        float2 v = g_Tzi[tid*MM + kz];
        tw[kz] = pk2(v.x, -v.y);     // (tc, ts)
    }
    __syncthreads();
    float* dst = out + bi * (size_t)(NN*NN);
    for (int yp = 0; yp < 96; yp++) {
        u64 e0=0, e1=0, o0=0, o1=0;
#pragma unroll
        for (int kz = 0; kz < MM; kz++) {
            ulonglong2 v = *(const ulonglong2*)&sg[kz*NN + 2*yp];
            if (kz & 1) { o0 = fma2(v.x, tw[kz], o0); o1 = fma2(v.y, tw[kz], o1); }
            else        { e0 = fma2(v.x, tw[kz], e0); e1 = fma2(v.y, tw[kz], e1); }
        }
        float2 E0 = up2(e0), E1 = up2(e1), O0 = up2(o0), O1 = up2(o1);
        float eA = E0.x + E0.y, oA = O0.x + O0.y;
        float eB = E1.x + E1.y, oB = O1.x + O1.y;
        const int y0 = 2*yp;
        dst[(size_t)y0*NN + tid]          = eA + oA;
        dst[(size_t)y0*NN + tid + 96]     = eA - oA;
        dst[(size_t)(y0+1)*NN + tid]      = eB + oB;
        dst[(size_t)(y0+1)*NN + tid + 96] = eB - oB;
    }
}

// ---------------- launch ------------------------------------------------------------
extern "C" void kernel_launch(void* const* d_in, const int* in_sizes, int n_in,
                              void* d_out, int out_size) {
    (void)in_sizes; (void)n_in; (void)out_size;
    const float* x  = (const float*)d_in[0];
    const float* wr = (const float*)d_in[1];
    const float* wi = (const float*)d_in[2];
    float* out = (float*)d_out;

    const int SM1 = (2*96*66)*4 + 96*MM*16;          // 75264 B
    const int SM2 = (2*96*17)*8 + 96*K32*16;         // 75264 B
    const int SM3 = (8*193 + NN*K32) * 8;            // 61504 B

    cudaFuncSetAttribute(k_fz, cudaFuncAttributeMaxDynamicSharedMemorySize, SM1);
    cudaFuncSetAttribute(k_fy, cudaFuncAttributeMaxDynamicSharedMemorySize, SM2);
    cudaFuncSetAttribute(k_fx, cudaFuncAttributeMaxDynamicSharedMemorySize, SM3);

    k_tables<<<1, 256>>>();
    k_fz <<<(CC*NN*NN)/64, 128, SM1>>>(x);        // 9216 blocks
    k_fy <<<(CC*NN*MM)/16, 256, SM2>>>();         // 3072 blocks
    k_fx <<<(CC*K32*MM)/8, 256, SM3>>>();         // 1024 blocks
    k_mix<<<K32*K32,       256>>>(wr, wi);        // 1024 blocks
    k_ix <<<(CC*K32*MM)/32, 96>>>();              // 256 blocks
    k_iy <<<(CC*NN*MM)/32,  96>>>();              // 1536 blocks
    k_iz <<<CC*NN,          96>>>(out);           // 3072 blocks
}